// round 1
// baseline (speedup 1.0000x reference)
#include <cuda_runtime.h>
#include <math.h>

#define BB 4096
#define TT 200
#define CC 16
#define HH 112
#define GG 448   // 4*H

#define NSTAT_BLK 256
#define STAT_THREADS 256

#define MB 32          // batch rows per CTA
#define TPB 896        // 8 m-groups x 112 j
#define NCTA (BB/MB)   // 128

// ---------------- device scratch (no allocations allowed) ----------------
__device__ float g_part[NSTAT_BLK * 32];          // per-block partial sums: [blk][cg*8 + w]
__device__ float g_Whh_il[HH * HH * 4];           // [(k*112 + j)*4 + g]
__device__ float g_Wih_il[CC * HH * 4];           // [(c*112 + j)*4 + g]  (BN-folded)
__device__ float g_bias_il[HH * 4];               // [j*4 + g]  effective bias

// ---------------- kernel 1: per-channel sum / sumsq (deterministic) ------
__global__ void k_stats(const float* __restrict__ x) {
    const int tid = threadIdx.x, bid = blockIdx.x;
    const float4* x4 = (const float4*)x;
    const int n4 = BB * TT * CC / 4;  // 3,276,800
    float4 s = make_float4(0.f, 0.f, 0.f, 0.f);
    float4 q = make_float4(0.f, 0.f, 0.f, 0.f);
    for (int i = bid * STAT_THREADS + tid; i < n4; i += NSTAT_BLK * STAT_THREADS) {
        float4 v = x4[i];
        s.x += v.x; s.y += v.y; s.z += v.z; s.w += v.w;
        q.x += v.x * v.x; q.y += v.y * v.y; q.z += v.z * v.z; q.w += v.w * v.w;
    }
    __shared__ float sm[STAT_THREADS][8];
    sm[tid][0] = s.x; sm[tid][1] = s.y; sm[tid][2] = s.z; sm[tid][3] = s.w;
    sm[tid][4] = q.x; sm[tid][5] = q.y; sm[tid][6] = q.z; sm[tid][7] = q.w;
    __syncthreads();
    // tree reduction stopping at stride 4 (channel-group preserving, fixed order)
    for (int st = STAT_THREADS / 2; st >= 4; st >>= 1) {
        if (tid < st) {
#pragma unroll
            for (int w = 0; w < 8; w++) sm[tid][w] += sm[tid + st][w];
        }
        __syncthreads();
    }
    if (tid < 4) {
#pragma unroll
        for (int w = 0; w < 8; w++) g_part[bid * 32 + tid * 8 + w] = sm[tid][w];
    }
}

// ---------------- kernel 2: finalize stats, fold BN, relayout weights ----
__global__ void k_prep(const float* __restrict__ gamma, const float* __restrict__ beta,
                       const float* __restrict__ W_ih, const float* __restrict__ W_hh,
                       const float* __restrict__ b_ih, const float* __restrict__ b_hh) {
    __shared__ float red[32];
    __shared__ float scale[CC], shift[CC];
    const int tid = threadIdx.x;
    if (tid < 32) {
        float a = 0.f;
        for (int b = 0; b < NSTAT_BLK; b++) a += g_part[b * 32 + tid];
        red[tid] = a;
    }
    __syncthreads();
    if (tid < CC) {
        const int cg = tid >> 2, qq = tid & 3;
        const float n = (float)(BB * TT);
        const float sum = red[cg * 8 + qq];
        const float ssq = red[cg * 8 + 4 + qq];
        const float mean = sum / n;
        const float var = ssq / n - mean * mean;
        const float sc = gamma[tid] * rsqrtf(var + 1e-5f);
        scale[tid] = sc;
        shift[tid] = beta[tid] - mean * sc;
    }
    __syncthreads();
    for (int nrow = tid; nrow < GG; nrow += blockDim.x) {
        const int g4 = nrow / HH, j = nrow % HH;
        float bsum = b_ih[nrow] + b_hh[nrow];
#pragma unroll
        for (int c = 0; c < CC; c++) {
            const float w = W_ih[nrow * CC + c];
            bsum += w * shift[c];
            g_Wih_il[(c * HH + j) * 4 + g4] = w * scale[c];
        }
        g_bias_il[j * 4 + g4] = bsum;
        for (int k = 0; k < HH; k++)
            g_Whh_il[(k * HH + j) * 4 + g4] = W_hh[nrow * HH + k];
    }
}

// ---------------- gate nonlinearities (accurate-fast) ---------------------
__device__ __forceinline__ float sigf(float z) {
    return __fdividef(1.f, 1.f + __expf(-z));
}
__device__ __forceinline__ float tanhf2(float z) {
    return 2.f * sigf(2.f * z) - 1.f;
}

// ---------------- kernel 3: persistent per-CTA LSTM -----------------------
// smem: Ws[112*112*4] (gate-interleaved W_hh, 200,704 B) + hx[128][32] (16,384 B)
__global__ void __launch_bounds__(TPB, 1)
k_lstm(const float* __restrict__ x, const float* __restrict__ W_fc,
       const float* __restrict__ b_fc, float* __restrict__ out) {
    extern __shared__ float smem[];
    float* Ws = smem;                    // 50176 floats
    float* hx = smem + HH * HH * 4;      // 128*32 floats, k-major: hx[k*MB + m]

    const int tid = threadIdx.x;
    const int m4 = (tid & 7) * 4;        // batch sub-row base (0..28)
    const int j = tid >> 3;              // hidden index 0..111
    const int b0 = blockIdx.x * MB;

    // stage W_hh into smem
    for (int i = tid; i < HH * HH * 4; i += TPB) Ws[i] = g_Whh_il[i];
    // zero h rows
    for (int i = tid; i < HH * MB; i += TPB) hx[i] = 0.f;

    // x loaders: first 128 threads; lm = batch row, lc = channel quad
    const int lm = tid & 31, lc = tid >> 5;
    float4 xreg = make_float4(0.f, 0.f, 0.f, 0.f);
    if (tid < 128)
        xreg = *(const float4*)&x[(b0 + lm) * (TT * CC) + 0 * CC + lc * 4];
    __syncthreads();
    if (tid < 128) {
        hx[(HH + lc * 4 + 0) * MB + lm] = xreg.x;
        hx[(HH + lc * 4 + 1) * MB + lm] = xreg.y;
        hx[(HH + lc * 4 + 2) * MB + lm] = xreg.z;
        hx[(HH + lc * 4 + 3) * MB + lm] = xreg.w;
    }

    const float4 bias = *(const float4*)&g_bias_il[j * 4];
    float cst[4] = {0.f, 0.f, 0.f, 0.f};
    const float4* WihIl = (const float4*)g_Wih_il;
    __syncthreads();

    for (int t = 0; t < TT; t++) {
        // prefetch next timestep's x early (L2/DRAM latency hidden by k-loop)
        if (tid < 128 && t + 1 < TT)
            xreg = *(const float4*)&x[(b0 + lm) * (TT * CC) + (t + 1) * CC + lc * 4];

        float acc[4][4];
#pragma unroll
        for (int g = 0; g < 4; g++)
#pragma unroll
            for (int mm = 0; mm < 4; mm++) acc[g][mm] = 0.f;

        // input projection part: k = H..H+C-1, weights from L2 (hot, 28KB)
#pragma unroll
        for (int c = 0; c < CC; c++) {
            const float4 wv = __ldg(&WihIl[c * HH + j]);
            const float4 hv = *(const float4*)&hx[(HH + c) * MB + m4];
            acc[0][0] += hv.x * wv.x; acc[0][1] += hv.y * wv.x; acc[0][2] += hv.z * wv.x; acc[0][3] += hv.w * wv.x;
            acc[1][0] += hv.x * wv.y; acc[1][1] += hv.y * wv.y; acc[1][2] += hv.z * wv.y; acc[1][3] += hv.w * wv.y;
            acc[2][0] += hv.x * wv.z; acc[2][1] += hv.y * wv.z; acc[2][2] += hv.z * wv.z; acc[2][3] += hv.w * wv.z;
            acc[3][0] += hv.x * wv.w; acc[3][1] += hv.y * wv.w; acc[3][2] += hv.z * wv.w; acc[3][3] += hv.w * wv.w;
        }

        // recurrent part: k = 0..111, both operands in smem (2x LDS.128 + 16 FFMA / k)
#pragma unroll 4
        for (int k = 0; k < HH; k++) {
            const float4 wv = *(const float4*)&Ws[(k * HH + j) * 4];
            const float4 hv = *(const float4*)&hx[k * MB + m4];
            acc[0][0] += hv.x * wv.x; acc[0][1] += hv.y * wv.x; acc[0][2] += hv.z * wv.x; acc[0][3] += hv.w * wv.x;
            acc[1][0] += hv.x * wv.y; acc[1][1] += hv.y * wv.y; acc[1][2] += hv.z * wv.y; acc[1][3] += hv.w * wv.y;
            acc[2][0] += hv.x * wv.z; acc[2][1] += hv.y * wv.z; acc[2][2] += hv.z * wv.z; acc[2][3] += hv.w * wv.z;
            acc[3][0] += hv.x * wv.w; acc[3][1] += hv.y * wv.w; acc[3][2] += hv.z * wv.w; acc[3][3] += hv.w * wv.w;
        }

        // gates + state update (thread-local c)
        float hnew[4];
#pragma unroll
        for (int mm = 0; mm < 4; mm++) {
            const float ig = sigf(acc[0][mm] + bias.x);
            const float fg = sigf(acc[1][mm] + bias.y);
            const float gg = tanhf2(acc[2][mm] + bias.z);
            const float og = sigf(acc[3][mm] + bias.w);
            const float cn = fg * cst[mm] + ig * gg;
            cst[mm] = cn;
            hnew[mm] = og * tanhf2(cn);
        }

        __syncthreads();  // all reads of hx for this step complete
        *(float4*)&hx[j * MB + m4] = make_float4(hnew[0], hnew[1], hnew[2], hnew[3]);
        if (tid < 128 && t + 1 < TT) {
            hx[(HH + lc * 4 + 0) * MB + lm] = xreg.x;
            hx[(HH + lc * 4 + 1) * MB + lm] = xreg.y;
            hx[(HH + lc * 4 + 2) * MB + lm] = xreg.z;
            hx[(HH + lc * 4 + 3) * MB + lm] = xreg.w;
        }
        __syncthreads();  // new h / x visible for next step
    }

    // final FC: out[b][o] = tanh(h . W_fc[o] + b_fc[o]), o in 0..5
    if (tid < 192) {
        const int m = tid & 31;
        const int o = tid >> 5;
        float s = b_fc[o];
        for (int jj = 0; jj < HH; jj++)
            s += hx[jj * MB + m] * W_fc[o * HH + jj];
        out[(b0 + m) * 6 + o] = tanhf2(s);
    }
}

// ---------------- launch ---------------------------------------------------
extern "C" void kernel_launch(void* const* d_in, const int* in_sizes, int n_in,
                              void* d_out, int out_size) {
    const float* x     = (const float*)d_in[0];
    const float* gamma = (const float*)d_in[1];
    const float* beta  = (const float*)d_in[2];
    const float* W_ih  = (const float*)d_in[3];
    const float* W_hh  = (const float*)d_in[4];
    const float* b_ih  = (const float*)d_in[5];
    const float* b_hh  = (const float*)d_in[6];
    const float* W_fc  = (const float*)d_in[7];
    const float* b_fc  = (const float*)d_in[8];
    float* out = (float*)d_out;

    const int smem_bytes = (HH * HH * 4 + 128 * MB) * (int)sizeof(float);  // 217,088
    cudaFuncSetAttribute(k_lstm, cudaFuncAttributeMaxDynamicSharedMemorySize, smem_bytes);

    k_stats<<<NSTAT_BLK, STAT_THREADS>>>(x);
    k_prep<<<1, GG>>>(gamma, beta, W_ih, W_hh, b_ih, b_hh);
    k_lstm<<<NCTA, TPB, smem_bytes>>>(x, W_fc, b_fc, out);
}